// round 7
// baseline (speedup 1.0000x reference)
#include <cuda_runtime.h>
#include <cuda_bf16.h>
#include <math.h>

#define NS   25      // n_shot * n_way (support samples)
#define NW   5       // n_way
#define NV   125     // QP variables
#define DIM  640
#define NQ   75
#define MAXB 512
#define TQP  160     // 5 warps for k_qp

// ------------------- global scratch (static, no allocations) -------------------
__device__ float g_ftu[(size_t)MAXB * NS * DIM];  // transformed (unnormalized) train feats
__device__ float g_invn[MAXB * NS];               // 1/norm of transformed train rows
__device__ float g_M[(size_t)MAXB * NS * NS];     // M = K_norm + I
__device__ float g_xsol[MAXB * NV];               // QP best_x

// ------------------- simple_transform -------------------
__device__ __forceinline__ float simp_g(float u) {
    float t = __logf(__fdividef(1.0f, u + 1e-5f) + 1.0f);
    return __powf(t, -1.3f);
}
// f(x) = sign(x) * (g(|x|) - g(0)); exactly pos+neg of the reference
__device__ __forceinline__ float simp(float x, float c0) {
    float g = simp_g(fabsf(x));
    return (x >= 0.0f) ? (g - c0) : (c0 - g);
}

// =====================================================================
// Kernel 1: transform train features, row norms, normalized Gram, M
// =====================================================================
__global__ void __launch_bounds__(256) k_prep(const float* __restrict__ ftrain,
                                              const int* __restrict__ usp) {
    __shared__ float tile[NS * 321];   // padded rows -> conflict-free
    __shared__ float Kacc[NS * NS];
    __shared__ float invn[NS];
    int b = blockIdx.x, tid = threadIdx.x;
    int us = usp ? (usp[0] != 0) : 1;
    float c0 = simp_g(0.0f);

    for (int e = tid; e < NS * NS; e += 256) Kacc[e] = 0.0f;

    const float* fb = ftrain + (size_t)b * NS * DIM;
    float* fo = g_ftu + (size_t)b * NS * DIM;

    for (int ch = 0; ch < 2; ch++) {
        __syncthreads();
        for (int e = tid; e < NS * 320; e += 256) {
            int r = e / 320, c = e - r * 320;
            float v = fb[r * DIM + ch * 320 + c];
            if (us) v = simp(v, c0);
            tile[r * 321 + c] = v;
            fo[r * DIM + ch * 320 + c] = v;
        }
        __syncthreads();
        for (int e = tid; e < NS * NS; e += 256) {
            int r = e / NS, r2 = e - r * NS;
            if (r2 < r) continue;               // upper triangle only
            const float* a = tile + r * 321;
            const float* bb = tile + r2 * 321;
            float acc = 0.0f;
            #pragma unroll 4
            for (int c = 0; c < 320; c++) acc = fmaf(a[c], bb[c], acc);
            Kacc[e] += acc;
        }
    }
    __syncthreads();
    if (tid < NS) {
        float n = sqrtf(Kacc[tid * NS + tid]);      // diag = ||t_r||^2
        float iv = 1.0f / fmaxf(n, 1e-12f);
        invn[tid] = iv;
        g_invn[b * NS + tid] = iv;
    }
    __syncthreads();
    for (int e = tid; e < NS * NS; e += 256) {
        int r = e / NS, c = e - r * NS;
        float kv = (c >= r) ? Kacc[e] : Kacc[c * NS + r];
        g_M[(size_t)b * NS * NS + e] = kv * invn[r] * invn[c] + ((r == c) ? 1.0f : 0.0f);
    }
}

// =====================================================================
// Kernel 2: QP via IPM — one CTA (5 warps) per batch element
// =====================================================================
struct QPShared {
    float M[625];
    float Hinv[NW][625];   // cholesky workspace -> becomes H_w^{-1}
    float Bbuf[NW][625];   // L^{-1} scratch
    float Smat[625];       // S_y, chol'ed in place
    float SB[625];         // L_S^{-1}
    float Sinv[625];
    float x[NV], s_[NV], z_[NV], bestx[NV], d_[NV];
    float rx[NV], rz[NV], r1[NV], uv[NV], rsc[NV];
    float dxa[NV], dsa[NV], dza[NV];
    float dxc[NV], dsc[NV], dzc[NV];
    float y_[NS], ry[NS], gvec[NS], dya[NS], dyc[NS];
    float red[8];
};

__device__ __forceinline__ float blk_sum5(float v, volatile float* red) {
    int tid = threadIdx.x;
    __syncthreads();
    #pragma unroll
    for (int o = 16; o; o >>= 1) v += __shfl_down_sync(0xffffffffu, v, o);
    if ((tid & 31) == 0) red[tid >> 5] = v;
    __syncthreads();
    return red[0] + red[1] + red[2] + red[3] + red[4];
}
__device__ __forceinline__ float blk_min5(float v, volatile float* red) {
    int tid = threadIdx.x;
    __syncthreads();
    #pragma unroll
    for (int o = 16; o; o >>= 1) v = fminf(v, __shfl_down_sync(0xffffffffu, v, o));
    if ((tid & 31) == 0) red[tid >> 5] = v;
    __syncthreads();
    return fminf(fminf(fminf(red[0], red[1]), fminf(red[2], red[3])), red[4]);
}

// warp-cooperative 25x25 Cholesky (in place, lower)
__device__ void chol25(float* A, int ln) {
    for (int j = 0; j < NS; j++) {
        float Ajj = A[j * NS + j];
        __syncwarp();
        float Ljj = sqrtf(Ajj);
        float inv = 1.0f / Ljj;
        if (ln == j) A[j * NS + j] = Ljj;
        else if (ln > j && ln < NS) A[ln * NS + j] *= inv;
        __syncwarp();
        if (ln > j && ln < NS) {
            float Lij = A[ln * NS + j];
            for (int k = j + 1; k <= ln; k++)
                A[ln * NS + k] = fmaf(-Lij, A[k * NS + j], A[ln * NS + k]);
        }
        __syncwarp();
    }
}
// B = L^{-1} (lane = column), upper zeroed
__device__ void trinv25(const float* L, float* B, int ln) {
    if (ln < NS) {
        int j = ln;
        for (int i = 0; i < j; i++) B[i * NS + j] = 0.0f;
        B[j * NS + j] = 1.0f / L[j * NS + j];
        for (int i = j + 1; i < NS; i++) {
            float ssum = 0.0f;
            for (int k = j; k < i; k++) ssum = fmaf(L[i * NS + k], B[k * NS + j], ssum);
            B[i * NS + j] = -ssum / L[i * NS + i];
        }
    }
    __syncwarp();
}
// Out = B^T B  (= (L L^T)^{-1}); lane = row
__device__ void ltl25(const float* B, float* Out, int ln) {
    if (ln < NS) {
        int i = ln;
        for (int j = 0; j < NS; j++) {
            int k0 = (i > j) ? i : j;
            float acc = 0.0f;
            for (int k = k0; k < NS; k++) acc = fmaf(B[k * NS + i], B[k * NS + j], acc);
            Out[i * NS + j] = acc;
        }
    }
    __syncwarp();
}

__device__ void factorize(QPShared& S) {
    int tid = threadIdx.x, wp = tid >> 5, ln = tid & 31;
    float* A = S.Hinv[wp];
    for (int e = ln; e < 625; e += 32) {
        int i = e / NS, j = e - i * NS;
        float v = S.M[e];
        if (i == j) v += S.d_[i * NW + wp];
        A[e] = v;
    }
    __syncwarp();
    chol25(A, ln);
    trinv25(A, S.Bbuf[wp], ln);
    ltl25(S.Bbuf[wp], A, ln);                 // A = H_w^{-1}
    __syncthreads();
    for (int e = tid; e < 625; e += TQP)
        S.Smat[e] = S.Hinv[0][e] + S.Hinv[1][e] + S.Hinv[2][e] + S.Hinv[3][e] + S.Hinv[4][e];
    __syncthreads();
    if (wp == 0) {
        chol25(S.Smat, ln);
        trinv25(S.Smat, S.SB, ln);
        ltl25(S.SB, S.Sinv, ln);
    }
    __syncthreads();
}

// KKT apply: NULL pointer == zero vector
__device__ void applyKKT(QPShared& S, const float* rx, const float* rs,
                         const float* rz, const float* ry,
                         float* dx, float* ds, float* dz, float* dy) {
    int tid = threadIdx.x, wp = tid >> 5, ln = tid & 31;
    if (tid < NV) {
        float rxv = rx ? rx[tid] : 0.0f;
        float rsv = rs ? rs[tid] : 0.0f;
        float rzv = rz ? rz[tid] : 0.0f;
        S.r1[tid] = -rxv - S.d_[tid] * rzv + rsv;
    }
    __syncthreads();
    if (ln < NS) {                      // u_w = H_w^{-1} r1_w
        const float* Hi = S.Hinv[wp] + ln * NS;
        float acc = 0.0f;
        #pragma unroll
        for (int j = 0; j < NS; j++) acc = fmaf(Hi[j], S.r1[j * NW + wp], acc);
        S.uv[ln * NW + wp] = acc;
    }
    __syncthreads();
    if (tid < NS) {
        float g = S.uv[tid * NW] + S.uv[tid * NW + 1] + S.uv[tid * NW + 2]
                + S.uv[tid * NW + 3] + S.uv[tid * NW + 4];
        if (ry) g += ry[tid];
        S.gvec[tid] = g;
    }
    __syncthreads();
    if (wp == 0 && ln < NS) {           // dy = S_y^{-1} g
        const float* Si = S.Sinv + ln * NS;
        float acc = 0.0f;
        #pragma unroll
        for (int j = 0; j < NS; j++) acc = fmaf(Si[j], S.gvec[j], acc);
        dy[ln] = acc;
    }
    __syncthreads();
    if (ln < NS) {                      // dx = u - H^{-1} A^T dy
        const float* Hi = S.Hinv[wp] + ln * NS;
        float acc = 0.0f;
        #pragma unroll
        for (int j = 0; j < NS; j++) acc = fmaf(Hi[j], dy[j], acc);
        dx[ln * NW + wp] = S.uv[ln * NW + wp] - acc;
    }
    __syncthreads();
    if (tid < NV) {
        float rsv = rs ? rs[tid] : 0.0f;
        float rzv = rz ? rz[tid] : 0.0f;
        float dxv = dx[tid];
        dz[tid] = S.d_[tid] * (dxv + rzv) - rsv;
        ds[tid] = -dxv - rzv;
    }
    __syncthreads();
}

__global__ void __launch_bounds__(TQP) k_qp() {
    __shared__ QPShared S;
    int b = blockIdx.x, tid = threadIdx.x;
    for (int e = tid; e < 625; e += TQP) S.M[e] = g_M[(size_t)b * 625 + e];
    if (tid < NV) {
        S.d_[tid] = 1.0f;
        int sidx = tid / NW, w = tid - sidx * NW;
        float oh = ((sidx % NW) == w) ? 1.0f : 0.0f;
        S.rx[tid] = -oh;          // p
        S.rz[tid] = -0.1f * oh;   // -h
    }
    __syncthreads();
    factorize(S);
    applyKKT(S, S.rx, nullptr, S.rz, nullptr, S.x, S.s_, S.z_, S.y_);
    // shift s, z
    float mv = (tid < NV) ? S.s_[tid] : 3.0e38f;
    float m = blk_min5(mv, S.red);
    if (tid < NV && m < 0.0f) S.s_[tid] -= (m - 1.0f);
    mv = (tid < NV) ? S.z_[tid] : 3.0e38f;
    m = blk_min5(mv, S.red);
    if (tid < NV && m < 0.0f) S.z_[tid] -= (m - 1.0f);
    __syncthreads();

    float best_res = 3.0e38f;
    int wp = tid >> 5, ln = tid & 31;
    for (int it = 0; it < 3; it++) {
        // residuals
        if (ln < NS) {
            const float* Mr = S.M + ln * NS;
            float qx = 0.0f;
            #pragma unroll
            for (int j = 0; j < NS; j++) qx = fmaf(Mr[j], S.x[j * NW + wp], qx);
            int v = ln * NW + wp;
            float oh = ((ln % NW) == wp) ? 1.0f : 0.0f;
            S.rx[v] = S.y_[ln] + S.z_[v] + qx - oh;
            S.rz[v] = S.x[v] + S.s_[v] - 0.1f * oh;
        }
        if (tid < NS)
            S.ry[tid] = S.x[tid * NW] + S.x[tid * NW + 1] + S.x[tid * NW + 2]
                      + S.x[tid * NW + 3] + S.x[tid * NW + 4];
        float szv = (tid < NV) ? S.s_[tid] * S.z_[tid] : 0.0f;
        float sz = blk_sum5(szv, S.red);          // also barriers the writes above
        float mu = fabsf(sz) * (1.0f / 125.0f);
        float t2 = (tid < NV) ? S.rx[tid] * S.rx[tid] : 0.0f;
        float nrx = sqrtf(blk_sum5(t2, S.red) + 1e-30f);
        t2 = (tid < NV) ? S.rz[tid] * S.rz[tid] : 0.0f;
        float nrz = sqrtf(blk_sum5(t2, S.red) + 1e-30f);
        t2 = (tid < NS) ? S.ry[tid] * S.ry[tid] : 0.0f;
        float nry = sqrtf(blk_sum5(t2, S.red) + 1e-30f);
        float res = nrz + nry + nrx + 125.0f * mu;
        if (res < best_res) { best_res = res; if (tid < NV) S.bestx[tid] = S.x[tid]; }
        if (it == 2) break;

        if (tid < NV) S.d_[tid] = S.z_[tid] / S.s_[tid];
        __syncthreads();
        factorize(S);
        // affine
        applyKKT(S, S.rx, S.z_, S.rz, S.ry, S.dxa, S.dsa, S.dza, S.dya);
        float az = (tid < NV) ? ((S.dza[tid] < 0.0f) ? -S.z_[tid] / S.dza[tid] : 1e12f) : 1e12f;
        float as = (tid < NV) ? ((S.dsa[tid] < 0.0f) ? -S.s_[tid] / S.dsa[tid] : 1e12f) : 1e12f;
        float alpha = fminf(blk_min5(fminf(az, as), S.red), 1.0f);
        float tt = (tid < NV) ? (S.s_[tid] + alpha * S.dsa[tid]) * (S.z_[tid] + alpha * S.dza[tid]) : 0.0f;
        float sumt = blk_sum5(tt, S.red);
        float ratio = sumt / sz;
        float musig = mu * ratio * ratio * ratio;
        if (tid < NV) S.rsc[tid] = (-musig + S.dsa[tid] * S.dza[tid]) / S.s_[tid];
        __syncthreads();
        // corrector
        applyKKT(S, nullptr, S.rsc, nullptr, nullptr, S.dxc, S.dsc, S.dzc, S.dyc);
        if (tid < NV) { S.dxa[tid] += S.dxc[tid]; S.dsa[tid] += S.dsc[tid]; S.dza[tid] += S.dzc[tid]; }
        if (tid < NS) S.dya[tid] += S.dyc[tid];
        __syncthreads();
        az = (tid < NV) ? ((S.dza[tid] < 0.0f) ? -S.z_[tid] / S.dza[tid] : 1e12f) : 1e12f;
        as = (tid < NV) ? ((S.dsa[tid] < 0.0f) ? -S.s_[tid] / S.dsa[tid] : 1e12f) : 1e12f;
        alpha = fminf(0.999f * blk_min5(fminf(az, as), S.red), 1.0f);
        if (tid < NV) {
            S.x[tid]  += alpha * S.dxa[tid];
            S.s_[tid] += alpha * S.dsa[tid];
            S.z_[tid] += alpha * S.dza[tid];
        }
        if (tid < NS) S.y_[tid] += alpha * S.dya[tid];
        __syncthreads();
    }
    if (tid < NV) g_xsol[(size_t)b * NV + tid] = S.bestx[tid];
}

// =====================================================================
// Kernel 3: W = (x * invn)^T ftu, then out[q,w] = <W_w, t(fq_q)> / ||t(fq_q)||
// =====================================================================
__global__ void __launch_bounds__(256) k_out(const float* __restrict__ ftest,
                                             const int* __restrict__ usp,
                                             float* __restrict__ out) {
    __shared__ float W[NW * DIM];
    __shared__ float xs[NV];
    int b = blockIdx.x, tid = threadIdx.x;
    int us = usp ? (usp[0] != 0) : 1;
    float c0 = simp_g(0.0f);
    if (tid < NV) xs[tid] = g_xsol[(size_t)b * NV + tid] * g_invn[b * NS + tid / NW];
    __syncthreads();
    const float* fu = g_ftu + (size_t)b * NS * DIM;
    for (int dd = tid; dd < DIM; dd += 256) {
        float a0 = 0, a1 = 0, a2 = 0, a3 = 0, a4 = 0;
        #pragma unroll
        for (int s = 0; s < NS; s++) {
            float fv = fu[s * DIM + dd];
            a0 = fmaf(xs[s * NW + 0], fv, a0);
            a1 = fmaf(xs[s * NW + 1], fv, a1);
            a2 = fmaf(xs[s * NW + 2], fv, a2);
            a3 = fmaf(xs[s * NW + 3], fv, a3);
            a4 = fmaf(xs[s * NW + 4], fv, a4);
        }
        W[0 * DIM + dd] = a0; W[1 * DIM + dd] = a1; W[2 * DIM + dd] = a2;
        W[3 * DIM + dd] = a3; W[4 * DIM + dd] = a4;
    }
    __syncthreads();
    int wp = tid >> 5, ln = tid & 31;
    const float* fq = ftest + (size_t)b * NQ * DIM;
    for (int q = wp; q < NQ; q += 8) {
        const float* row = fq + (size_t)q * DIM;
        float ss = 0, d0 = 0, d1 = 0, d2 = 0, d3 = 0, d4 = 0;
        for (int dd = ln; dd < DIM; dd += 32) {
            float v = row[dd];
            if (us) v = simp(v, c0);
            ss = fmaf(v, v, ss);
            d0 = fmaf(W[dd], v, d0);
            d1 = fmaf(W[DIM + dd], v, d1);
            d2 = fmaf(W[2 * DIM + dd], v, d2);
            d3 = fmaf(W[3 * DIM + dd], v, d3);
            d4 = fmaf(W[4 * DIM + dd], v, d4);
        }
        #pragma unroll
        for (int o = 16; o; o >>= 1) {
            ss += __shfl_down_sync(0xffffffffu, ss, o);
            d0 += __shfl_down_sync(0xffffffffu, d0, o);
            d1 += __shfl_down_sync(0xffffffffu, d1, o);
            d2 += __shfl_down_sync(0xffffffffu, d2, o);
            d3 += __shfl_down_sync(0xffffffffu, d3, o);
            d4 += __shfl_down_sync(0xffffffffu, d4, o);
        }
        if (ln == 0) {
            float iq = 1.0f / fmaxf(sqrtf(ss), 1e-12f);
            float* o = out + ((size_t)b * NQ + q) * NW;
            o[0] = d0 * iq; o[1] = d1 * iq; o[2] = d2 * iq; o[3] = d3 * iq; o[4] = d4 * iq;
        }
    }
}

extern "C" void kernel_launch(void* const* d_in, const int* in_sizes, int n_in,
                              void* d_out, int out_size) {
    const float* ftest  = (const float*)d_in[0];
    const float* ftrain = (const float*)d_in[1];
    const int* usp = (n_in > 4) ? (const int*)d_in[4] : nullptr; // nonzero bits => true (works for int or float 1)
    int B = in_sizes[1] / (NS * DIM);
    if (B > MAXB) B = MAXB;
    if (B < 1) B = 1;
    k_prep<<<B, 256>>>(ftrain, usp);
    k_qp<<<B, TQP>>>();
    k_out<<<B, 256>>>(ftest, usp, (float*)d_out);
}